// round 4
// baseline (speedup 1.0000x reference)
#include <cuda_runtime.h>
#include <math.h>

#define ENC_LEVELS 80
#define NPAIRS     (ENC_LEVELS / 2)   // 40 float4 per position

// Per-level fp32 scales: fl32( fl32(1.25^i) * fl32(pi) )  (bitwise-validated R2/R3)
__device__ float g_scales[ENC_LEVELS];
// Exponent-indexed phase table: T[Ev] = frac(2^(Ev-150) / (2*pi)) in 2^-64 fixed point.
// For v = m * 2^(Ev-150) (m = 24-bit mantissa), frac(v/2pi) = frac(m * T[Ev]/2^64).
__device__ unsigned long long g_T[256];

__global__ void pe_init_kernel() {
    int ev = threadIdx.x;   // 0..255
    if (ev >= 256) return;

    if (ev < ENC_LEVELS) {
        // 1.25^i by binary powering in double: rel err ~1.5e-15 -> correctly
        // rounded fp32 after cast. Then one f32 multiply by float(pi).
        double b = 1.25, s = 1.0;
        int ii = ev;
        while (ii) { if (ii & 1) s *= b; b *= b; ii >>= 1; }
        g_scales[ev] = (float)s * (float)M_PI;
    }

    // 1/(2*pi) in double-double: c ~= ch + cl, ~106 bits.
    const double th = 6.283185307179586476925286766559;   // 2pi (rounds to hi)
    const double tl = 2.4492935982947063545e-16;          // 2pi - (double)2pi
    double ch = 1.0 / th;
    double r  = fma(ch, th, -1.0) + ch * tl;              // ch*(2pi) - 1
    double cl = -r * ch;                                  // correction term

    int k = ev - 150;                                     // v = m * 2^k
    double A  = ldexp(ch, k);                             // exact scaling
    double B  = ldexp(cl, k);                             // exact scaling
    double Af = A - floor(A);                             // frac(A), exact

    // F = round((Af + B) * 2^64), assembled in two 32-bit halves.
    double hi_d  = floor(Af * 4294967296.0);              // exact product
    double rem   = Af * 4294967296.0 - hi_d;              // exact
    double lo_d  = floor((rem + B * 4294967296.0) * 4294967296.0);
    unsigned long long F =
        ((unsigned long long)(long long)hi_d << 32) +
        (unsigned long long)(long long)lo_d;              // mod-2^64 wrap = mod-1, correct
    g_T[ev] = F;   // ev=0 -> F~0 -> v=0 gives sin=0, cos=1 exactly
}

#define TWO_PI_F 6.28318530717958647692f

// (sin, cos) of v = fl32(pf*s) via exponent-table fixed-point reduction.
__device__ __forceinline__ float2 pe_pair(float pf, float s,
                                          const unsigned long long* __restrict__ sT) {
    float v = __fmul_rn(pf, s);
    unsigned int iv = __float_as_uint(v);
    unsigned long long T = sT[iv >> 23];                  // LDS.64
    unsigned int m   = (iv & 0x7FFFFFu) | 0x800000u;      // 24-bit mantissa
    unsigned int Tlo = (unsigned int)T;
    unsigned int Thi = (unsigned int)(T >> 32);
    // top 32 bits of (m*T mod 2^64), +0.5 turn for signed centering
    unsigned int h = __umulhi(m, Tlo) + m * Thi + 0x80000000u;
    float uf = __uint_as_float(0x3F800000u | (h >> 9));   // 1 + frac'
    float theta = (uf - 1.5f) * TWO_PI_F;                 // in [-pi, pi), exact sub
    float2 sc;
    sc.x = __sinf(theta);                                 // MUFU.SIN
    sc.y = __cosf(theta);                                 // MUFU.COS
    return sc;
}

// blockDim (40, 8): lane x owns level pair (2x, 2x+1) -> one float4 per p.
__global__ void __launch_bounds__(320) pe_main_kernel(float4* __restrict__ out, int n) {
    __shared__ unsigned long long sT[256];
    int t = threadIdx.y * NPAIRS + threadIdx.x;
    if (t < 256) sT[t] = g_T[t];

    int x = threadIdx.x;                    // 0..39
    float s0 = __ldg(&g_scales[2 * x]);
    float s1 = __ldg(&g_scales[2 * x + 1]);
    __syncthreads();

    int p  = blockIdx.x * 8 + threadIdx.y;
    int ps = gridDim.x * 8;
    float pf  = (float)p;                   // exact: p < 2^24
    float pfs = (float)ps;
    float4* op = out + (size_t)p * NPAIRS + x;
    size_t  os = (size_t)ps * NPAIRS;

    for (; p < n; p += ps, pf += pfs, op += os) {
        float2 a = pe_pair(pf, s0, sT);
        float2 b = pe_pair(pf, s1, sT);
        float4 r;
        r.x = a.x; r.y = a.y; r.z = b.x; r.w = b.y;
        __stcs(op, r);                      // streaming store: don't thrash L2
    }
}

extern "C" void kernel_launch(void* const* d_in, const int* in_sizes, int n_in,
                              void* d_out, int out_size) {
    (void)d_in; (void)n_in; (void)out_size; // reference ignores pos values
    int n = in_sizes[0];

    pe_init_kernel<<<1, 256>>>();

    int blocks = 148 * 6;                   // one balanced wave, 60/64 warps/SM
    int max_needed = (n + 7) / 8;
    if (blocks > max_needed) blocks = max_needed;
    dim3 bd(NPAIRS, 8);
    pe_main_kernel<<<blocks, bd>>>((float4*)d_out, n);
}

// round 5
// speedup vs baseline: 1.0361x; 1.0361x over previous
#include <cuda_runtime.h>

#define ENC_LEVELS 80
#define NPAIRS     (ENC_LEVELS / 2)   // 40 float4 per position

// ---------------------------------------------------------------------------
// Compile-time tables (no init kernel, single graph node).
//
// For v = m * 2^(Ev-150) (fp32: m = 24-bit mantissa, Ev = biased exponent):
//     frac(v / 2pi) = frac(m * frac(2^(Ev-150) / 2pi))
// and frac(2^k / 2pi) is the 64-bit bit-window of the binary expansion of
// 1/(2pi) starting at bit k+1, i.e. bits (k-1 .. k+62) of 2/pi (shift by 2).
// ---------------------------------------------------------------------------
namespace petab {

// fdlibm two_over_pi: fractional bits of 2/pi in 24-bit chunks (288 bits;
// only bits up to ~88 are reachable since v <= 7.1e13 -> Ev <= 173).
constexpr unsigned int TP[12] = {
    0xA2F983, 0x6E4E44, 0x1529FC, 0x2757D1, 0xF534DD, 0xC0DB62,
    0x95993C, 0x439041, 0xFE5163, 0xABDEBB, 0xC561B7, 0x246E3A
};

constexpr int tp_bit(int i) {          // bit i (1-indexed) of frac(2/pi)
    if (i < 1 || i > 12 * 24) return 0;
    int c = (i - 1) / 24, b = (i - 1) % 24;
    return (int)((TP[c] >> (23 - b)) & 1u);
}

constexpr unsigned long long make_T(int ev) {
    int k = ev - 150;
    unsigned long long t = 0;
    for (int j = 0; j < 64; j++)       // bits k+1..k+64 of 1/2pi = k-1..k+62 of 2/pi
        t = (t << 1) | (unsigned long long)tp_bit(k - 1 + j);
    t += (unsigned long long)tp_bit(k + 63);   // round-to-nearest (mod-2^64 wrap ok)
    return t;
}

constexpr double pow125(int i) {       // binary powering in double (rel err ~1e-15)
    double b = 1.25, s = 1.0;
    while (i) { if (i & 1) s *= b; b *= b; i >>= 1; }
    return s;
}

struct Tables {
    unsigned long long T[256];
    float S[ENC_LEVELS];
    constexpr Tables() : T(), S() {
        for (int e = 0; e < 256; e++) T[e] = make_T(e);
        for (int i = 0; i < ENC_LEVELS; i++)
            S[i] = (float)pow125(i) * 3.14159265358979323846f;  // * fl32(pi)
    }
};

} // namespace petab

__device__ constexpr petab::Tables g_tab = petab::Tables();

#define TWO_PI_F 6.28318530717958647692f

// (sin, cos) of v = fl32(pf*s) via exponent-table fixed-point reduction.
__device__ __forceinline__ float2 pe_pair(float pf, float s,
                                          const unsigned long long* __restrict__ sT) {
    float v = __fmul_rn(pf, s);
    unsigned int iv = __float_as_uint(v);
    unsigned long long T = sT[iv >> 23];                    // LDS.64
    unsigned int m   = (iv & 0x7FFFFFu) | 0x800000u;        // 24-bit mantissa
    unsigned int Tlo = (unsigned int)T;
    unsigned int Thi = (unsigned int)(T >> 32);
    // top 32 bits of (m*T mod 2^64), +0.5 turn for signed centering
    unsigned int h = __umulhi(m, Tlo) + m * Thi + 0x80000000u;
    float uf = __uint_as_float(0x3F800000u | (h >> 9));     // 1 + frac'
    float theta = (uf - 1.5f) * TWO_PI_F;                   // [-pi, pi)
    float2 sc;
    sc.x = __sinf(theta);                                   // MUFU.SIN
    sc.y = __cosf(theta);                                   // MUFU.COS
    return sc;
}

// blockDim (40, 8): lane x owns level pair (2x, 2x+1).
// Each thread handles rows p and p+8 per iteration (2 independent chains,
// 2 batched STG.128) and grid-strides by 16*gridDim.x positions.
__global__ void __launch_bounds__(320) pe_main_kernel(float4* __restrict__ out, int n) {
    __shared__ unsigned long long sT[256];
    int t = threadIdx.y * NPAIRS + threadIdx.x;
    if (t < 256) sT[t] = g_tab.T[t];

    int x = threadIdx.x;                     // 0..39
    float s0 = g_tab.S[2 * x];
    float s1 = g_tab.S[2 * x + 1];
    __syncthreads();

    int p      = blockIdx.x * 16 + threadIdx.y;
    int stride = gridDim.x * 16;
    float pf   = (float)p;                   // exact: p < 2^24
    float pfs  = (float)stride;
    float4* op = out + (size_t)p * NPAIRS + x;
    size_t  os = (size_t)stride * NPAIRS;

    for (; p < n; p += stride, pf += pfs, op += os) {
        float2 a0 = pe_pair(pf, s0, sT);
        float2 b0 = pe_pair(pf, s1, sT);
        float4 r0; r0.x = a0.x; r0.y = a0.y; r0.z = b0.x; r0.w = b0.y;
        op[0] = r0;

        if (p + 8 < n) {
            float pf1 = pf + 8.0f;
            float2 a1 = pe_pair(pf1, s0, sT);
            float2 b1 = pe_pair(pf1, s1, sT);
            float4 r1; r1.x = a1.x; r1.y = a1.y; r1.z = b1.x; r1.w = b1.y;
            op[(size_t)8 * NPAIRS] = r1;
        }
    }
}

extern "C" void kernel_launch(void* const* d_in, const int* in_sizes, int n_in,
                              void* d_out, int out_size) {
    (void)d_in; (void)n_in; (void)out_size;  // reference ignores pos values
    int n = in_sizes[0];

    int blocks = 148 * 6;                    // 60/64 warps per SM, one wave
    int max_needed = (n + 15) / 16;
    if (blocks > max_needed) blocks = max_needed;
    if (blocks < 1) blocks = 1;
    dim3 bd(NPAIRS, 8);
    pe_main_kernel<<<blocks, bd>>>((float4*)d_out, n);
}

// round 6
// speedup vs baseline: 1.0445x; 1.0081x over previous
#include <cuda_runtime.h>

#define ENC_LEVELS 80
#define NPAIRS     (ENC_LEVELS / 2)   // 40 float4 per position

// ---------------------------------------------------------------------------
// Compile-time tables (no init kernel, single graph node).
//
// For v = m * 2^(Ev-150) (fp32: m = 24-bit mantissa, Ev = biased exponent):
//     frac(v / 2pi) = frac(m * frac(2^(Ev-150) / 2pi))
// and frac(2^k / 2pi) is the 64-bit bit-window of the binary expansion of
// 2/pi (shifted by 2) starting at bit k-1.
// ---------------------------------------------------------------------------
namespace petab {

// fdlibm two_over_pi: fractional bits of 2/pi in 24-bit chunks.
constexpr unsigned int TP[12] = {
    0xA2F983, 0x6E4E44, 0x1529FC, 0x2757D1, 0xF534DD, 0xC0DB62,
    0x95993C, 0x439041, 0xFE5163, 0xABDEBB, 0xC561B7, 0x246E3A
};

constexpr int tp_bit(int i) {          // bit i (1-indexed) of frac(2/pi)
    if (i < 1 || i > 12 * 24) return 0;
    int c = (i - 1) / 24, b = (i - 1) % 24;
    return (int)((TP[c] >> (23 - b)) & 1u);
}

constexpr unsigned long long make_T(int ev) {
    int k = ev - 150;
    unsigned long long t = 0;
    for (int j = 0; j < 64; j++)       // bits k+1..k+64 of 1/2pi
        t = (t << 1) | (unsigned long long)tp_bit(k - 1 + j);
    t += (unsigned long long)tp_bit(k + 63);   // round (mod-2^64 wrap ok)
    return t;
}

constexpr double pow125(int i) {       // binary powering in double
    double b = 1.25, s = 1.0;
    while (i) { if (i & 1) s *= b; b *= b; i >>= 1; }
    return s;
}

struct Tables {
    unsigned long long T[256];
    float S[ENC_LEVELS];
    constexpr Tables() : T(), S() {
        for (int e = 0; e < 256; e++) T[e] = make_T(e);
        for (int i = 0; i < ENC_LEVELS; i++)
            S[i] = (float)pow125(i) * 3.14159265358979323846f;  // * fl32(pi)
    }
};

} // namespace petab

__device__ constexpr petab::Tables g_tab = petab::Tables();

#define TWO_PI_F 6.28318530717958647692f

// (sin, cos) of v = fl32(pf*s) via exponent-table fixed-point reduction.
__device__ __forceinline__ float2 pe_pair(float pf, float s,
                                          const unsigned long long* __restrict__ sT) {
    float v = __fmul_rn(pf, s);
    unsigned int iv = __float_as_uint(v);
    unsigned long long T = sT[iv >> 23];                    // LDS.64
    unsigned int m   = (iv & 0x7FFFFFu) | 0x800000u;        // 24-bit mantissa
    unsigned int Tlo = (unsigned int)T;
    unsigned int Thi = (unsigned int)(T >> 32);
    // top 32 bits of (m*T mod 2^64), +0.5 turn for signed centering
    unsigned int h = __umulhi(m, Tlo) + m * Thi + 0x80000000u;
    float uf = __uint_as_float(0x3F800000u | (h >> 9));     // 1 + frac'
    float theta = (uf - 1.5f) * TWO_PI_F;                   // [-pi, pi)
    float2 sc;
    sc.x = __sinf(theta);                                   // MUFU.SIN
    sc.y = __cosf(theta);                                   // MUFU.COS
    return sc;
}

__device__ __forceinline__ float4 pe_row(float pf, float s0, float s1,
                                         const unsigned long long* __restrict__ sT) {
    float2 a = pe_pair(pf, s0, sT);
    float2 b = pe_pair(pf, s1, sT);
    float4 r; r.x = a.x; r.y = a.y; r.z = b.x; r.w = b.y;
    return r;
}

// blockDim (40, 8): lane x owns level pair (2x, 2x+1).
// 4-way position unroll: rows p, p+8, p+16, p+24 per iteration — 4 independent
// compute chains and 4 batched STG.128 per thread for store MLP.
__global__ void __launch_bounds__(320, 6) pe_main_kernel(float4* __restrict__ out, int n) {
    __shared__ unsigned long long sT[256];
    int t = threadIdx.y * NPAIRS + threadIdx.x;
    if (t < 256) sT[t] = g_tab.T[t];

    int x = threadIdx.x;                     // 0..39
    float s0 = g_tab.S[2 * x];
    float s1 = g_tab.S[2 * x + 1];
    __syncthreads();

    int p      = blockIdx.x * 32 + threadIdx.y;
    int stride = gridDim.x * 32;
    float pf   = (float)p;                   // exact: p < 2^24
    float pfs  = (float)stride;
    float4* op = out + (size_t)p * NPAIRS + x;
    size_t  os = (size_t)stride * NPAIRS;
    const size_t R = (size_t)8 * NPAIRS;     // 8 rows of float4

    for (; p < n; p += stride, pf += pfs, op += os) {
        float4 r0 = pe_row(pf,         s0, s1, sT);
        if (p + 24 < n) {                    // fast path: all 4 rows valid
            float4 r1 = pe_row(pf + 8.0f,  s0, s1, sT);
            float4 r2 = pe_row(pf + 16.0f, s0, s1, sT);
            float4 r3 = pe_row(pf + 24.0f, s0, s1, sT);
            op[0]     = r0;
            op[R]     = r1;
            op[2 * R] = r2;
            op[3 * R] = r3;
        } else {                             // tail
            op[0] = r0;
            if (p +  8 < n) op[R]     = pe_row(pf +  8.0f, s0, s1, sT);
            if (p + 16 < n) op[2 * R] = pe_row(pf + 16.0f, s0, s1, sT);
        }
    }
}

extern "C" void kernel_launch(void* const* d_in, const int* in_sizes, int n_in,
                              void* d_out, int out_size) {
    (void)d_in; (void)n_in; (void)out_size;  // reference ignores pos values
    int n = in_sizes[0];

    int blocks = 148 * 6;                    // 60/64 warps per SM
    int max_needed = (n + 31) / 32;
    if (blocks > max_needed) blocks = max_needed;
    if (blocks < 1) blocks = 1;
    dim3 bd(NPAIRS, 8);
    pe_main_kernel<<<blocks, bd>>>((float4*)d_out, n);
}

// round 7
// speedup vs baseline: 1.0762x; 1.0304x over previous
#include <cuda_runtime.h>

#define ENC_LEVELS 80
#define NPAIRS     (ENC_LEVELS / 2)   // 40 float4 per position

// ---------------------------------------------------------------------------
// Compile-time tables. For v = m * 2^(Ev-150) (fp32 bits):
//   frac(v / 2pi) = frac(m * frac(2^(Ev-150) / 2pi))
// T[Ev] = frac(2^(Ev-150)/2pi) in 2^-64 fixed point, from the bits of 2/pi.
// ---------------------------------------------------------------------------
namespace petab {

constexpr unsigned int TP[12] = {   // fdlibm two_over_pi, 24-bit chunks
    0xA2F983, 0x6E4E44, 0x1529FC, 0x2757D1, 0xF534DD, 0xC0DB62,
    0x95993C, 0x439041, 0xFE5163, 0xABDEBB, 0xC561B7, 0x246E3A
};

constexpr int tp_bit(int i) {       // bit i (1-indexed) of frac(2/pi)
    if (i < 1 || i > 12 * 24) return 0;
    int c = (i - 1) / 24, b = (i - 1) % 24;
    return (int)((TP[c] >> (23 - b)) & 1u);
}

constexpr unsigned long long make_T(int ev) {
    int k = ev - 150;
    unsigned long long t = 0;
    for (int j = 0; j < 64; j++)
        t = (t << 1) | (unsigned long long)tp_bit(k - 1 + j);
    t += (unsigned long long)tp_bit(k + 63);   // round (mod-2^64 wrap ok)
    return t;
}

constexpr double pow125(int i) {
    double b = 1.25, s = 1.0;
    while (i) { if (i & 1) s *= b; b *= b; i >>= 1; }
    return s;
}

struct Tables {
    unsigned long long T[256];
    float S[ENC_LEVELS];
    constexpr Tables() : T(), S() {
        for (int e = 0; e < 256; e++) T[e] = make_T(e);
        for (int i = 0; i < ENC_LEVELS; i++)
            S[i] = (float)pow125(i) * 3.14159265358979323846f;  // * fl32(pi)
    }
};

} // namespace petab

__device__ constexpr petab::Tables g_tab = petab::Tables();

#define TWO_PI_F 6.28318530717958647692f

// (sin, cos) of v = fl32(pf*s) via exponent-table fixed-point reduction.
__device__ __forceinline__ float2 pe_pair(float pf, float s,
                                          const unsigned long long* __restrict__ sT) {
    float v = __fmul_rn(pf, s);
    unsigned int iv = __float_as_uint(v);
    unsigned long long T = sT[iv >> 23];                    // LDS.64
    unsigned int m   = (iv & 0x7FFFFFu) | 0x800000u;        // 24-bit mantissa
    unsigned int Tlo = (unsigned int)T;
    unsigned int Thi = (unsigned int)(T >> 32);
    unsigned int h = __umulhi(m, Tlo) + m * Thi + 0x80000000u;  // +0.5 turn center
    float uf = __uint_as_float(0x3F800000u | (h >> 9));     // 1 + frac'
    float theta = (uf - 1.5f) * TWO_PI_F;                   // [-pi, pi)
    float2 sc;
    sc.x = __sinf(theta);                                   // MUFU.SIN
    sc.y = __cosf(theta);                                   // MUFU.COS
    return sc;
}

// One quad (float4) = levels (2x, 2x+1) of position p, where q = p*40 + x.
__device__ __forceinline__ float4 pe_quad(unsigned int q,
                                          const unsigned long long* __restrict__ sT,
                                          const float2* __restrict__ sS) {
    unsigned int p = q / 40u;          // UMULHI magic
    unsigned int x = q - p * 40u;
    float pf = (float)p;               // exact: p < 2^24
    float2 s = sS[x];                  // LDS.64
    float2 a = pe_pair(pf, s.x, sT);
    float2 b = pe_pair(pf, s.y, sT);
    float4 r; r.x = a.x; r.y = a.y; r.z = b.x; r.w = b.y;
    return r;
}

// Flat mapping: 256-thread blocks (8 blocks/SM = 64 warps resident).
// Each thread covers quads q, q+256, q+512, q+768 per grid-stride iteration:
// 4 independent chains, 4 coalesced batched STG.128.
__global__ void __launch_bounds__(256, 8) pe_main_kernel(float4* __restrict__ out,
                                                         unsigned int nq) {
    __shared__ unsigned long long sT[256];
    __shared__ float2 sS[NPAIRS];
    int t = threadIdx.x;
    sT[t] = g_tab.T[t];
    if (t < NPAIRS) sS[t] = make_float2(g_tab.S[2 * t], g_tab.S[2 * t + 1]);
    __syncthreads();

    unsigned int q      = blockIdx.x * 1024u + (unsigned int)t;
    unsigned int stride = gridDim.x * 1024u;

    for (; q < nq; q += stride) {
        unsigned int q1 = q + 256u, q2 = q + 512u, q3 = q + 768u;
        if (q3 < nq) {                       // fast path: all 4 valid
            float4 r0 = pe_quad(q,  sT, sS);
            float4 r1 = pe_quad(q1, sT, sS);
            float4 r2 = pe_quad(q2, sT, sS);
            float4 r3 = pe_quad(q3, sT, sS);
            out[q]  = r0;
            out[q1] = r1;
            out[q2] = r2;
            out[q3] = r3;
        } else {                             // tail
            out[q] = pe_quad(q, sT, sS);
            if (q1 < nq) out[q1] = pe_quad(q1, sT, sS);
            if (q2 < nq) out[q2] = pe_quad(q2, sT, sS);
        }
    }
}

extern "C" void kernel_launch(void* const* d_in, const int* in_sizes, int n_in,
                              void* d_out, int out_size) {
    (void)d_in; (void)n_in; (void)out_size;  // reference ignores pos values
    unsigned int n  = (unsigned int)in_sizes[0];
    unsigned int nq = n * (unsigned int)NPAIRS;   // total float4 quads (20M)

    int blocks = 148 * 8;                    // 64/64 warps per SM, one wave
    unsigned int max_needed = (nq + 1023u) / 1024u;
    if ((unsigned int)blocks > max_needed) blocks = (int)max_needed;
    if (blocks < 1) blocks = 1;
    pe_main_kernel<<<blocks, 256>>>((float4*)d_out, nq);
}